// round 14
// baseline (speedup 1.0000x reference)
#include <cuda_runtime.h>
#include <cuda_fp16.h>
#include <cstdint>
#include <cstddef>

#define GPTS   8192
#define NBATCH 32
#define OCH    128
#define TN     64
#define NTILE  (GPTS / TN)          // 128 g-tiles
#define NB     (NBATCH * NTILE)     // 4096 gemm CTAs per layer
#define KSEC   32
#define EPSV   1e-5f
#define SLOPE  0.1f

// SMEM byte offsets (dynamic)
// buffer: [Wh 8K | Xh 4K] = 12KB, x2 = 24KB
#define SMB_BUF    0
#define SMB_AF     24576    // affine a[128], c[128]
#define SMB_BIAS   25600    // bias[128]
#define SMB_SUM    26112    // sSum/sSqr/sMax/sMin 4x256 floats = 4KB
#define SMB_DYN    30720

// ---------------- device scratch ----------------
__device__ float d_Y0[(size_t)NBATCH * OCH * GPTS];
__device__ float d_Y1[(size_t)NBATCH * OCH * GPTS];
__device__ float d_Psum[(size_t)OCH * NB];
__device__ float d_Psq [(size_t)OCH * NB];
__device__ float d_Pmax[(size_t)OCH * NB];
__device__ float d_Pmin[(size_t)OCH * NB];
__device__ __half d_Whi[4 * OCH * 192];
__device__ float d_W2T[4 * OCH * OCH];
__device__ float d_Bias[NBATCH * OCH];
__device__ float d_Aa[2 * OCH];
__device__ float d_Cc[2 * OCH];

// ---------------- helpers ----------------
__device__ __forceinline__ uint32_t smem_u32(const void* p) {
    uint32_t a;
    asm("{ .reg .u64 t; cvta.to.shared.u64 t, %1; cvt.u32.u64 %0, t; }" : "=r"(a) : "l"(p));
    return a;
}
__device__ __forceinline__ void ldsm4(uint32_t* r, uint32_t addr) {
    asm volatile("ldmatrix.sync.aligned.m8n8.x4.shared.b16 {%0,%1,%2,%3}, [%4];"
        : "=r"(r[0]), "=r"(r[1]), "=r"(r[2]), "=r"(r[3]) : "r"(addr));
}
__device__ __forceinline__ void mma16816(float* c, const uint32_t* a, const uint32_t* b) {
    asm volatile("mma.sync.aligned.m16n8k16.row.col.f32.f16.f16.f32 "
        "{%0,%1,%2,%3}, {%4,%5,%6,%7}, {%8,%9}, {%0,%1,%2,%3};"
        : "+f"(c[0]), "+f"(c[1]), "+f"(c[2]), "+f"(c[3])
        : "r"(a[0]), "r"(a[1]), "r"(a[2]), "r"(a[3]), "r"(b[0]), "r"(b[1]));
}
__device__ __forceinline__ uint32_t swz_off(int row, int kc) {
    return (uint32_t)(row * 64 + ((((kc >> 3) ^ ((row >> 1) & 3)) << 4)) + (kc & 7) * 2);
}
__device__ __forceinline__ float leaky(float v) { return fmaxf(v, SLOPE * v); }

// ---------------- prep: fold all weights to fp16 + W2 transpose ----------------
__global__ void prep_w_all(const float* __restrict__ W1, const float* __restrict__ W2,
                           const float* __restrict__ W3, const float* __restrict__ W4)
{
    int idx = blockIdx.x * blockDim.x + threadIdx.x;
    int nfold = 4 * OCH * 192;
    if (idx < nfold) {
        int L = idx / (OCH * 192);
        int r = idx - L * (OCH * 192);
        int o = r / 192, c = r % 192;
        const float* W = (L == 0) ? W1 : (L == 1) ? W2 : (L == 2) ? W3 : W4;
        int Cin = (L == 0) ? 64 : 128;
        int Kw = 2 * Cin + 3;
        float v = 0.f;
        if (c < Cin)          v = W[o * Kw + c] + W[o * Kw + Cin + c];
        else if (c < Cin + 3) v = W[o * Kw + 2 * Cin + (c - Cin)];
        d_Whi[idx] = __float2half_rn(v);
    } else {
        int r2 = idx - nfold;
        if (r2 < 4 * OCH * OCH) {
            int L = r2 / (OCH * OCH);
            int t = r2 - L * (OCH * OCH);
            int c = t >> 7, o = t & 127;
            const float* W = (L == 0) ? W1 : (L == 1) ? W2 : (L == 2) ? W3 : W4;
            int Cin = (L == 0) ? 64 : 128;
            int Kw = 2 * Cin + 3;
            d_W2T[r2] = (c < Cin) ? W[o * Kw + Cin + c] : 0.f;
        }
    }
}

// ---------------- prep: per-batch x0 bias ----------------
__global__ void prep_bias(const float* __restrict__ W2T, int Cin,
                          const float* __restrict__ X,
                          const float* __restrict__ aP, const float* __restrict__ cP)
{
    __shared__ float x0[OCH];
    __shared__ float part[256];
    int b = blockIdx.x, tid = threadIdx.x;
    if (tid < Cin) {
        float x = X[(size_t)b * Cin * GPTS + (size_t)tid * GPTS];
        if (aP) x = leaky(fmaf(aP[tid], x, cP[tid]));
        x0[tid] = x;
    }
    __syncthreads();
    int o = tid & 127, h = tid >> 7;
    int half = Cin >> 1;
    float acc = 0.f;
#pragma unroll 4
    for (int c = h * half; c < (h + 1) * half; c++)
        acc = fmaf(W2T[c * OCH + o], x0[c], acc);
    part[tid] = acc;
    __syncthreads();
    if (tid < OCH) d_Bias[b * OCH + tid] = part[tid] + part[tid + 128];
}

// ---------------- HMMA GEMM layer (1-term, 128x64 tile, occ 3) ----------------
template<bool DOMAX>
__global__ void __launch_bounds__(256, 3)
gemm_mm(const float* __restrict__ X, int Cin, int nsec,
        const __half* __restrict__ Wfold,
        const float* __restrict__ ev,
        const float* __restrict__ aP, const float* __restrict__ cP,
        float* __restrict__ Y)
{
    extern __shared__ __align__(16) char smem[];
    uint32_t sb = smem_u32(smem);

    const int tid = threadIdx.x, lane = tid & 31, wid = tid >> 5;
    const int wm = wid >> 1, wn = wid & 1;           // 4(M) x 2(N)
    const int gt = blockIdx.x, b = blockIdx.y;
    const int g0 = gt * TN;
    const int ctaIdx = b * NTILE + gt;
    const bool useAff = (aP != nullptr);
    const int CinTot = Cin + 3;

    float* afp = (float*)(smem + SMB_AF);
    float* sB  = (float*)(smem + SMB_BIAS);
    if (tid < OCH) {
        afp[tid] = useAff ? aP[tid] : 1.f;
        afp[OCH + tid] = useAff ? cP[tid] : 0.f;
        sB[tid] = d_Bias[b * OCH + tid];
    }
    __syncthreads();

    const float* xb  = X  + (size_t)b * Cin * GPTS + g0;
    const float* evb = ev + (size_t)b * 3   * GPTS + g0;
    const uint32_t* Wh32 = (const uint32_t*)Wfold;

    const int lg = tid & 63, chh = tid >> 6;         // g, 8-ch group 0..3

    float xr[8];

    float c[2][4][4];
#pragma unroll
    for (int mi = 0; mi < 2; mi++)
#pragma unroll
        for (int ni = 0; ni < 4; ni++)
#pragma unroll
            for (int e = 0; e < 4; e++) c[mi][ni][e] = 0.f;

    auto ldgX = [&](int s) {
#pragma unroll
        for (int j = 0; j < 8; j++) {
            int ch = s * KSEC + chh * 8 + j;
            float v = 0.f;
            if (ch < Cin)            v = xb[(size_t)ch * GPTS + lg];
            else if (ch < CinTot)    v = evb[(size_t)(ch - Cin) * GPTS + lg];
            xr[j] = v;
        }
    };
    auto stsX = [&](int s, int buf) {
        uint32_t XhO = SMB_BUF + buf * 12288 + 8192;
#pragma unroll
        for (int j = 0; j < 8; j++) {
            int ch = s * KSEC + chh * 8 + j;
            if (useAff && ch < Cin) xr[j] = leaky(fmaf(afp[ch], xr[j], afp[OCH + ch]));
        }
        uint32_t hq[4];
#pragma unroll
        for (int q = 0; q < 4; q++) {
            __half2 hp = __float22half2_rn(make_float2(xr[2 * q], xr[2 * q + 1]));
            hq[q] = *(uint32_t*)&hp;
        }
        uint32_t off = (uint32_t)(lg * 64 + (((chh ^ ((lg >> 1) & 3)) << 4)));
        *(uint4*)(smem + XhO + off) = make_uint4(hq[0], hq[1], hq[2], hq[3]);
    };
    auto stsW = [&](int s, int buf) {
        uint32_t WhO = SMB_BUF + buf * 12288;
#pragma unroll
        for (int i = 0; i < 8; i++) {
            int idx = tid + i * 256;
            int o = idx >> 4, kp = idx & 15;
            uint32_t vh = Wh32[o * 96 + s * 16 + kp];
            uint32_t off = swz_off(o, kp * 2);
            *(uint32_t*)(smem + WhO + off) = vh;
        }
    };

    ldgX(0);
    stsX(0, 0);
    stsW(0, 0);

    for (int s = 0; s < nsec; s++) {
        int buf = s & 1;
        __syncthreads();
        if (s + 1 < nsec) ldgX(s + 1);

        uint32_t WhB = sb + SMB_BUF + buf * 12288;
        uint32_t XhB = WhB + 8192;
#pragma unroll
        for (int ks = 0; ks < 2; ks++) {
            if (s * KSEC + ks * 16 >= CinTot) break;   // all-zero K16 chunk
            uint32_t ah[2][4], bh[4][2];
#pragma unroll
            for (int mi = 0; mi < 2; mi++) {
                int row = wm * 32 + mi * 16 + (lane & 15);
                int chunk = 2 * ks + (lane >> 4);
                uint32_t off = (uint32_t)(row * 64 + (((chunk ^ ((row >> 1) & 3)) << 4)));
                ldsm4(ah[mi], WhB + off);
            }
#pragma unroll
            for (int p = 0; p < 2; p++) {
                int row = wn * 32 + p * 16 + (lane & 7) + ((lane >> 4) << 3);
                int chunk = 2 * ks + ((lane >> 3) & 1);
                uint32_t off = (uint32_t)(row * 64 + (((chunk ^ ((row >> 1) & 3)) << 4)));
                uint32_t t[4];
                ldsm4(t, XhB + off);
                bh[2 * p][0] = t[0]; bh[2 * p][1] = t[1];
                bh[2 * p + 1][0] = t[2]; bh[2 * p + 1][1] = t[3];
            }
#pragma unroll
            for (int mi = 0; mi < 2; mi++)
#pragma unroll
                for (int ni = 0; ni < 4; ni++) mma16816(c[mi][ni], ah[mi], bh[ni]);
        }

        if (s + 1 < nsec) {
            stsX(s + 1, buf ^ 1);
            stsW(s + 1, buf ^ 1);
        }
    }

    // ---------------- register-direct epilogue ----------------
    float* sSum = (float*)(smem + SMB_SUM);   // [128][2]
    float* sSqr = sSum + 256;
    float* sMax = sSqr + 256;
    float* sMin = sMax + 256;
    float* Yb = Y + (size_t)b * OCH * GPTS + g0;

#pragma unroll
    for (int mi = 0; mi < 2; mi++) {
        int r0 = wm * 32 + mi * 16 + (lane >> 2);
        float b0 = sB[r0], b1 = sB[r0 + 8];
        float s0 = 0.f, q0 = 0.f, s1 = 0.f, q1 = 0.f;
        float m0 = -3.4e38f, n0 = 3.4e38f, m1 = -3.4e38f, n1 = 3.4e38f;
#pragma unroll
        for (int ni = 0; ni < 4; ni++) {
            float v0 = c[mi][ni][0] - b0;
            float v1 = c[mi][ni][1] - b0;
            float v2 = c[mi][ni][2] - b1;
            float v3 = c[mi][ni][3] - b1;
            s0 += v0 + v1; q0 += v0 * v0 + v1 * v1;
            s1 += v2 + v3; q1 += v2 * v2 + v3 * v3;
            if (DOMAX) {
                m0 = fmaxf(m0, fmaxf(v0, v1)); n0 = fminf(n0, fminf(v0, v1));
                m1 = fmaxf(m1, fmaxf(v2, v3)); n1 = fminf(n1, fminf(v2, v3));
            } else {
                int col = wn * 32 + ni * 8 + 2 * (lane & 3);
                *(float2*)(Yb + (size_t)r0 * GPTS + col)       = make_float2(v0, v1);
                *(float2*)(Yb + (size_t)(r0 + 8) * GPTS + col) = make_float2(v2, v3);
            }
        }
#pragma unroll
        for (int sh = 1; sh <= 2; sh <<= 1) {
            s0 += __shfl_xor_sync(0xFFFFFFFFu, s0, sh);
            q0 += __shfl_xor_sync(0xFFFFFFFFu, q0, sh);
            s1 += __shfl_xor_sync(0xFFFFFFFFu, s1, sh);
            q1 += __shfl_xor_sync(0xFFFFFFFFu, q1, sh);
            if (DOMAX) {
                m0 = fmaxf(m0, __shfl_xor_sync(0xFFFFFFFFu, m0, sh));
                n0 = fminf(n0, __shfl_xor_sync(0xFFFFFFFFu, n0, sh));
                m1 = fmaxf(m1, __shfl_xor_sync(0xFFFFFFFFu, m1, sh));
                n1 = fminf(n1, __shfl_xor_sync(0xFFFFFFFFu, n1, sh));
            }
        }
        if ((lane & 3) == 0) {
            sSum[r0 * 2 + wn] = s0;       sSqr[r0 * 2 + wn] = q0;
            sSum[(r0 + 8) * 2 + wn] = s1; sSqr[(r0 + 8) * 2 + wn] = q1;
            if (DOMAX) {
                sMax[r0 * 2 + wn] = m0;       sMin[r0 * 2 + wn] = n0;
                sMax[(r0 + 8) * 2 + wn] = m1; sMin[(r0 + 8) * 2 + wn] = n1;
            }
        }
    }
    __syncthreads();
    if (tid < OCH) {
        float s = sSum[tid * 2] + sSum[tid * 2 + 1];
        float q = sSqr[tid * 2] + sSqr[tid * 2 + 1];
        d_Psum[(size_t)tid * NB + ctaIdx] = s;
        d_Psq [(size_t)tid * NB + ctaIdx] = q;
        if (DOMAX) {
            d_Pmax[(size_t)tid * NB + ctaIdx] = fmaxf(sMax[tid * 2], sMax[tid * 2 + 1]);
            d_Pmin[(size_t)tid * NB + ctaIdx] = fminf(sMin[tid * 2], sMin[tid * 2 + 1]);
        }
    }
}

// ---------------- stats (1024 threads, one float4 per thread); LAST finalizes ----------------
template<bool LAST>
__global__ void stats_kernel(const float* __restrict__ gamma,
                             const float* __restrict__ beta,
                             float* __restrict__ aOut, float* __restrict__ cOut,
                             float* __restrict__ out)
{
    int o = blockIdx.x, tid = threadIdx.x;
    float4 vs = *(const float4*)(d_Psum + (size_t)o * NB + tid * 4);
    float4 vq = *(const float4*)(d_Psq  + (size_t)o * NB + tid * 4);
    float s = (vs.x + vs.y) + (vs.z + vs.w);
    float q = (vq.x + vq.y) + (vq.z + vq.w);
    __shared__ float ss[1024], sq[1024];
    __shared__ float sac[2];
    ss[tid] = s; sq[tid] = q;
    __syncthreads();
    for (int st = 512; st > 0; st >>= 1) {
        if (tid < st) { ss[tid] += ss[tid + st]; sq[tid] += sq[tid + st]; }
        __syncthreads();
    }
    if (tid == 0) {
        float N = (float)((size_t)NBATCH * GPTS);
        float m = ss[0] / N;
        float v = sq[0] / N - m * m;
        float inv = rsqrtf(v + EPSV);
        float a = gamma[o] * inv;
        float cc = beta[o] - a * m;
        aOut[o] = a;
        cOut[o] = cc;
        if (LAST) { sac[0] = a; sac[1] = cc; }
    }
    if (LAST) {
        __syncthreads();
        float a = sac[0], cc = sac[1];
        int b = tid >> 5, lane = tid & 31;
        const float* pm = d_Pmax + (size_t)o * NB + b * NTILE;
        const float* pn = d_Pmin + (size_t)o * NB + b * NTILE;
        float mx = fmaxf(fmaxf(pm[lane], pm[lane + 32]), fmaxf(pm[lane + 64], pm[lane + 96]));
        float mn = fminf(fminf(pn[lane], pn[lane + 32]), fminf(pn[lane + 64], pn[lane + 96]));
#pragma unroll
        for (int sh = 16; sh > 0; sh >>= 1) {
            mx = fmaxf(mx, __shfl_xor_sync(0xFFFFFFFFu, mx, sh));
            mn = fminf(mn, __shfl_xor_sync(0xFFFFFFFFu, mn, sh));
        }
        if (lane == 0) {
            float y = (a >= 0.f) ? mx : mn;
            out[b * OCH + o] = leaky(fmaf(a, y, cc));
        }
    }
}

// ---------------- launcher ----------------
extern "C" void kernel_launch(void* const* d_in, const int* in_sizes, int n_in,
                              void* d_out, int out_size)
{
    const float* feat = (const float*)d_in[0];
    const float* ev   = (const float*)d_in[1];
    const float* W[4] = {(const float*)d_in[2], (const float*)d_in[3],
                         (const float*)d_in[4], (const float*)d_in[5]};
    const float* gm[4] = {(const float*)d_in[6],  (const float*)d_in[8],
                          (const float*)d_in[10], (const float*)d_in[12]};
    const float* bt[4] = {(const float*)d_in[7],  (const float*)d_in[9],
                          (const float*)d_in[11], (const float*)d_in[13]};
    float* out = (float*)d_out;

    cudaFuncSetAttribute(gemm_mm<false>, cudaFuncAttributeMaxDynamicSharedMemorySize, SMB_DYN);
    cudaFuncSetAttribute(gemm_mm<true>,  cudaFuncAttributeMaxDynamicSharedMemorySize, SMB_DYN);

    float *y0, *y1, *aa, *cc, *w2t;
    __half* wh;
    cudaGetSymbolAddress((void**)&y0, d_Y0);
    cudaGetSymbolAddress((void**)&y1, d_Y1);
    cudaGetSymbolAddress((void**)&aa, d_Aa);
    cudaGetSymbolAddress((void**)&cc, d_Cc);
    cudaGetSymbolAddress((void**)&wh, d_Whi);
    cudaGetSymbolAddress((void**)&w2t, d_W2T);

    int prepN = 4 * OCH * 192 + 4 * OCH * OCH;
    prep_w_all<<<(prepN + 255) / 256, 256>>>(W[0], W[1], W[2], W[3]);

    float* ybuf[2] = {y0, y1};
    const float* cur = feat;
    int curC = 64;
    float* aPrev = nullptr;
    float* cPrev = nullptr;

    dim3 gg(NTILE, NBATCH);
    for (int L = 0; L < 4; L++) {
        int dst = L & 1;
        float* aCur = aa + dst * OCH;
        float* cCur = cc + dst * OCH;
        int nsec = (curC + 3 + KSEC - 1) / KSEC;      // 64->3, 128->5
        const __half* Wf = wh + (size_t)L * OCH * 192;
        const float* W2T = w2t + (size_t)L * OCH * OCH;
        prep_bias<<<NBATCH, 256>>>(W2T, curC, cur, aPrev, cPrev);
        if (L == 3) {
            gemm_mm<true><<<gg, 256, SMB_DYN>>>(cur, curC, nsec, Wf, ev, aPrev, cPrev, ybuf[dst]);
            stats_kernel<true><<<OCH, 1024>>>(gm[L], bt[L], aCur, cCur, out);
        } else {
            gemm_mm<false><<<gg, 256, SMB_DYN>>>(cur, curC, nsec, Wf, ev, aPrev, cPrev, ybuf[dst]);
            stats_kernel<false><<<OCH, 1024>>>(gm[L], bt[L], aCur, cCur, out);
        }
        cur = ybuf[dst];
        curC = OCH;
        aPrev = aCur;
        cPrev = cCur;
    }
}

// round 15
// speedup vs baseline: 1.0696x; 1.0696x over previous
#include <cuda_runtime.h>
#include <cuda_fp16.h>
#include <cstdint>
#include <cstddef>

#define GPTS   8192
#define NBATCH 32
#define OCH    128
#define TN     128
#define NTILE  (GPTS / TN)          // 64 g-tiles
#define NB     (NBATCH * NTILE)     // 2048 gemm CTAs per layer
#define KSEC   32
#define EPSV   1e-5f
#define SLOPE  0.1f

// SMEM byte offsets (dynamic)
#define SMB_W      0        // up to 6 sections x 8KB, resident whole kernel
#define SMB_X      49152    // 2 x 8KB X double buffer
#define SMB_AF     65536    // affine a[128], c[128]
#define SMB_BIAS   66560    // bias[128]
#define SMB_SUM    67072    // sSum/sSqr/sMax/sMin 4x512 floats = 8KB
#define SMB_DYN    75264

// ---------------- device scratch ----------------
__device__ float d_Y0[(size_t)NBATCH * OCH * GPTS];
__device__ float d_Y1[(size_t)NBATCH * OCH * GPTS];
__device__ float d_Psum[(size_t)OCH * NB];
__device__ float d_Psq [(size_t)OCH * NB];
__device__ float d_Pmax[(size_t)OCH * NB];
__device__ float d_Pmin[(size_t)OCH * NB];
__device__ uint32_t d_WhiSw[4 * 6 * 2048];   // pre-swizzled per-section SMEM images
__device__ float d_W2T[4 * OCH * OCH];
__device__ float d_Bias[NBATCH * OCH];
__device__ float d_Aa[2 * OCH];
__device__ float d_Cc[2 * OCH];

// ---------------- helpers ----------------
__device__ __forceinline__ uint32_t smem_u32(const void* p) {
    uint32_t a;
    asm("{ .reg .u64 t; cvta.to.shared.u64 t, %1; cvt.u32.u64 %0, t; }" : "=r"(a) : "l"(p));
    return a;
}
__device__ __forceinline__ void ldsm4(uint32_t* r, uint32_t addr) {
    asm volatile("ldmatrix.sync.aligned.m8n8.x4.shared.b16 {%0,%1,%2,%3}, [%4];"
        : "=r"(r[0]), "=r"(r[1]), "=r"(r[2]), "=r"(r[3]) : "r"(addr));
}
__device__ __forceinline__ void mma16816(float* c, const uint32_t* a, const uint32_t* b) {
    asm volatile("mma.sync.aligned.m16n8k16.row.col.f32.f16.f16.f32 "
        "{%0,%1,%2,%3}, {%4,%5,%6,%7}, {%8,%9}, {%0,%1,%2,%3};"
        : "+f"(c[0]), "+f"(c[1]), "+f"(c[2]), "+f"(c[3])
        : "r"(a[0]), "r"(a[1]), "r"(a[2]), "r"(a[3]), "r"(b[0]), "r"(b[1]));
}
__device__ __forceinline__ float leaky(float v) { return fmaxf(v, SLOPE * v); }

__device__ __forceinline__ float fold_w(const float* W, int Cin, int Kw, int o, int c) {
    if (c < Cin)       return W[o * Kw + c] + W[o * Kw + Cin + c];
    if (c < Cin + 3)   return W[o * Kw + 2 * Cin + (c - Cin)];
    return 0.f;
}

// ---------------- prep: fold weights to pre-swizzled fp16 images + W2T ----------------
__global__ void prep_w_all(const float* __restrict__ W1, const float* __restrict__ W2,
                           const float* __restrict__ W3, const float* __restrict__ W4)
{
    int idx = blockIdx.x * blockDim.x + threadIdx.x;
    int nsw = 4 * 6 * 2048;                 // uint32 elements of swizzled W
    if (idx < nsw) {
        int L = idx / 12288;
        int r = idx - L * 12288;
        int s = r >> 11;                    // section
        int t = r & 2047;
        int o = t >> 4, kp = t & 15;
        const float* W = (L == 0) ? W1 : (L == 1) ? W2 : (L == 2) ? W3 : W4;
        int Cin = (L == 0) ? 64 : 128;
        int Kw = 2 * Cin + 3;
        int c0 = s * KSEC + kp * 2;
        __half2 hp = __halves2half2(__float2half_rn(fold_w(W, Cin, Kw, o, c0)),
                                    __float2half_rn(fold_w(W, Cin, Kw, o, c0 + 1)));
        uint32_t off = (uint32_t)(o * 64 + ((((kp >> 2) ^ ((o >> 1) & 3)) << 4)) + (kp & 3) * 4);
        d_WhiSw[(L * 6 + s) * 2048 + (off >> 2)] = *(uint32_t*)&hp;
    } else {
        int r2 = idx - nsw;
        if (r2 < 4 * OCH * OCH) {
            int L = r2 / (OCH * OCH);
            int t = r2 - L * (OCH * OCH);
            int c = t >> 7, o = t & 127;
            const float* W = (L == 0) ? W1 : (L == 1) ? W2 : (L == 2) ? W3 : W4;
            int Cin = (L == 0) ? 64 : 128;
            int Kw = 2 * Cin + 3;
            d_W2T[r2] = (c < Cin) ? W[o * Kw + Cin + c] : 0.f;
        }
    }
}

// ---------------- prep: per-batch x0 bias ----------------
__global__ void prep_bias(const float* __restrict__ W2T, int Cin,
                          const float* __restrict__ X,
                          const float* __restrict__ aP, const float* __restrict__ cP)
{
    __shared__ float x0[OCH];
    __shared__ float part[256];
    int b = blockIdx.x, tid = threadIdx.x;
    if (tid < Cin) {
        float x = X[(size_t)b * Cin * GPTS + (size_t)tid * GPTS];
        if (aP) x = leaky(fmaf(aP[tid], x, cP[tid]));
        x0[tid] = x;
    }
    __syncthreads();
    int o = tid & 127, h = tid >> 7;
    int half = Cin >> 1;
    float acc = 0.f;
#pragma unroll 4
    for (int c = h * half; c < (h + 1) * half; c++)
        acc = fmaf(W2T[c * OCH + o], x0[c], acc);
    part[tid] = acc;
    __syncthreads();
    if (tid < OCH) d_Bias[b * OCH + tid] = part[tid] + part[tid + 128];
}

// ---------------- HMMA GEMM layer (1-term, W resident in smem) ----------------
template<bool DOMAX>
__global__ void __launch_bounds__(256, 2)
gemm_mm(const float* __restrict__ X, int Cin, int nsec,
        const uint32_t* __restrict__ Wsw,
        const float* __restrict__ ev,
        const float* __restrict__ aP, const float* __restrict__ cP,
        float* __restrict__ Y)
{
    extern __shared__ __align__(16) char smem[];
    uint32_t sb = smem_u32(smem);

    const int tid = threadIdx.x, lane = tid & 31, wid = tid >> 5;
    const int wm = wid >> 2, wn = wid & 3;
    const int gt = blockIdx.x, b = blockIdx.y;
    const int g0 = gt * TN;
    const int ctaIdx = b * NTILE + gt;
    const bool useAff = (aP != nullptr);
    const int CinTot = Cin + 3;

    float* afp = (float*)(smem + SMB_AF);
    float* sB  = (float*)(smem + SMB_BIAS);
    if (tid < OCH) {
        afp[tid] = useAff ? aP[tid] : 1.f;
        afp[OCH + tid] = useAff ? cP[tid] : 0.f;
        sB[tid] = d_Bias[b * OCH + tid];
    }
    // prologue W copy: nsec sections x 8KB, straight uint4 copies
    {
        const uint4* src = (const uint4*)Wsw;
        uint4* dst = (uint4*)(smem + SMB_W);
        int n = nsec * 512;
        for (int i = tid; i < n; i += 256) dst[i] = src[i];
    }

    const float* xb  = X  + (size_t)b * Cin * GPTS + g0;
    const float* evb = ev + (size_t)b * 3   * GPTS + g0;

    const int lg = tid & 127, chh = tid >> 7;

    float xr[16];

    float c[4][4][4];
#pragma unroll
    for (int mi = 0; mi < 4; mi++)
#pragma unroll
        for (int ni = 0; ni < 4; ni++)
#pragma unroll
            for (int e = 0; e < 4; e++) c[mi][ni][e] = 0.f;

    auto ldgX = [&](int s) {
#pragma unroll
        for (int j = 0; j < 16; j++) {
            int ch = s * KSEC + chh * 16 + j;
            float v = 0.f;
            if (ch < Cin)            v = xb[(size_t)ch * GPTS + lg];
            else if (ch < CinTot)    v = evb[(size_t)(ch - Cin) * GPTS + lg];
            xr[j] = v;
        }
    };
    auto stsX = [&](int s, int buf) {
        uint32_t XhO = SMB_X + buf * 8192;
#pragma unroll
        for (int j = 0; j < 16; j++) {
            int ch = s * KSEC + chh * 16 + j;
            if (useAff && ch < Cin) xr[j] = leaky(fmaf(afp[ch], xr[j], afp[OCH + ch]));
        }
#pragma unroll
        for (int grp = 0; grp < 2; grp++) {
            uint32_t hq[4];
#pragma unroll
            for (int q = 0; q < 4; q++) {
                __half2 hp = __float22half2_rn(
                    make_float2(xr[grp * 8 + 2 * q], xr[grp * 8 + 2 * q + 1]));
                hq[q] = *(uint32_t*)&hp;
            }
            int kcg = chh * 2 + grp;
            uint32_t off = (uint32_t)(lg * 64 + (((kcg ^ ((lg >> 1) & 3)) << 4)));
            *(uint4*)(smem + XhO + off) = make_uint4(hq[0], hq[1], hq[2], hq[3]);
        }
    };

    ldgX(0);
    stsX(0, 0);

    for (int s = 0; s < nsec; s++) {
        int buf = s & 1;
        __syncthreads();
        if (s + 1 < nsec) ldgX(s + 1);

        uint32_t WhB = sb + SMB_W + s * 8192;
        uint32_t XhB = sb + SMB_X + buf * 8192;
#pragma unroll
        for (int ks = 0; ks < 2; ks++) {
            if (s * KSEC + ks * 16 >= CinTot) break;   // all-zero K16 chunk
            uint32_t ah[4][4], bh[4][2];
#pragma unroll
            for (int mi = 0; mi < 4; mi++) {
                int row = wm * 64 + mi * 16 + (lane & 15);
                int chunk = 2 * ks + (lane >> 4);
                uint32_t off = (uint32_t)(row * 64 + (((chunk ^ ((row >> 1) & 3)) << 4)));
                ldsm4(ah[mi], WhB + off);
            }
#pragma unroll
            for (int p = 0; p < 2; p++) {
                int row = wn * 32 + p * 16 + (lane & 7) + ((lane >> 4) << 3);
                int chunk = 2 * ks + ((lane >> 3) & 1);
                uint32_t off = (uint32_t)(row * 64 + (((chunk ^ ((row >> 1) & 3)) << 4)));
                uint32_t t[4];
                ldsm4(t, XhB + off);
                bh[2 * p][0] = t[0]; bh[2 * p][1] = t[1];
                bh[2 * p + 1][0] = t[2]; bh[2 * p + 1][1] = t[3];
            }
#pragma unroll
            for (int mi = 0; mi < 4; mi++)
#pragma unroll
                for (int ni = 0; ni < 4; ni++) mma16816(c[mi][ni], ah[mi], bh[ni]);
        }

        if (s + 1 < nsec) stsX(s + 1, buf ^ 1);
    }

    // ---------------- register-direct epilogue ----------------
    float* sSum = (float*)(smem + SMB_SUM);   // [128][4]
    float* sSqr = sSum + 512;
    float* sMax = sSqr + 512;
    float* sMin = sMax + 512;
    float* Yb = Y + (size_t)b * OCH * GPTS + g0;

#pragma unroll
    for (int mi = 0; mi < 4; mi++) {
        int r0 = wm * 64 + mi * 16 + (lane >> 2);
        float b0 = sB[r0], b1 = sB[r0 + 8];
        float s0 = 0.f, q0 = 0.f, s1 = 0.f, q1 = 0.f;
        float m0 = -3.4e38f, n0 = 3.4e38f, m1 = -3.4e38f, n1 = 3.4e38f;
#pragma unroll
        for (int ni = 0; ni < 4; ni++) {
            float v0 = c[mi][ni][0] - b0;
            float v1 = c[mi][ni][1] - b0;
            float v2 = c[mi][ni][2] - b1;
            float v3 = c[mi][ni][3] - b1;
            s0 += v0 + v1; q0 += v0 * v0 + v1 * v1;
            s1 += v2 + v3; q1 += v2 * v2 + v3 * v3;
            if (DOMAX) {
                m0 = fmaxf(m0, fmaxf(v0, v1)); n0 = fminf(n0, fminf(v0, v1));
                m1 = fmaxf(m1, fmaxf(v2, v3)); n1 = fminf(n1, fminf(v2, v3));
            } else {
                int col = wn * 32 + ni * 8 + 2 * (lane & 3);
                *(float2*)(Yb + (size_t)r0 * GPTS + col)       = make_float2(v0, v1);
                *(float2*)(Yb + (size_t)(r0 + 8) * GPTS + col) = make_float2(v2, v3);
            }
        }
#pragma unroll
        for (int sh = 1; sh <= 2; sh <<= 1) {
            s0 += __shfl_xor_sync(0xFFFFFFFFu, s0, sh);
            q0 += __shfl_xor_sync(0xFFFFFFFFu, q0, sh);
            s1 += __shfl_xor_sync(0xFFFFFFFFu, s1, sh);
            q1 += __shfl_xor_sync(0xFFFFFFFFu, q1, sh);
            if (DOMAX) {
                m0 = fmaxf(m0, __shfl_xor_sync(0xFFFFFFFFu, m0, sh));
                n0 = fminf(n0, __shfl_xor_sync(0xFFFFFFFFu, n0, sh));
                m1 = fmaxf(m1, __shfl_xor_sync(0xFFFFFFFFu, m1, sh));
                n1 = fminf(n1, __shfl_xor_sync(0xFFFFFFFFu, n1, sh));
            }
        }
        if ((lane & 3) == 0) {
            sSum[r0 * 4 + wn] = s0;       sSqr[r0 * 4 + wn] = q0;
            sSum[(r0 + 8) * 4 + wn] = s1; sSqr[(r0 + 8) * 4 + wn] = q1;
            if (DOMAX) {
                sMax[r0 * 4 + wn] = m0;       sMin[r0 * 4 + wn] = n0;
                sMax[(r0 + 8) * 4 + wn] = m1; sMin[(r0 + 8) * 4 + wn] = n1;
            }
        }
    }
    __syncthreads();
    if (tid < OCH) {
        float s = (sSum[tid * 4] + sSum[tid * 4 + 1]) + (sSum[tid * 4 + 2] + sSum[tid * 4 + 3]);
        float q = (sSqr[tid * 4] + sSqr[tid * 4 + 1]) + (sSqr[tid * 4 + 2] + sSqr[tid * 4 + 3]);
        d_Psum[(size_t)tid * NB + ctaIdx] = s;
        d_Psq [(size_t)tid * NB + ctaIdx] = q;
        if (DOMAX) {
            float mx = fmaxf(fmaxf(sMax[tid * 4], sMax[tid * 4 + 1]),
                             fmaxf(sMax[tid * 4 + 2], sMax[tid * 4 + 3]));
            float mn = fminf(fminf(sMin[tid * 4], sMin[tid * 4 + 1]),
                             fminf(sMin[tid * 4 + 2], sMin[tid * 4 + 3]));
            d_Pmax[(size_t)tid * NB + ctaIdx] = mx;
            d_Pmin[(size_t)tid * NB + ctaIdx] = mn;
        }
    }
}

// ---------------- stats (1024 threads, one float2 per thread); LAST finalizes ----------------
template<bool LAST>
__global__ void stats_kernel(const float* __restrict__ gamma,
                             const float* __restrict__ beta,
                             float* __restrict__ aOut, float* __restrict__ cOut,
                             float* __restrict__ out)
{
    int o = blockIdx.x, tid = threadIdx.x;
    float2 vs = *(const float2*)(d_Psum + (size_t)o * NB + tid * 2);
    float2 vq = *(const float2*)(d_Psq  + (size_t)o * NB + tid * 2);
    float s = vs.x + vs.y;
    float q = vq.x + vq.y;
    __shared__ float ss[1024], sq[1024];
    __shared__ float sac[2];
    ss[tid] = s; sq[tid] = q;
    __syncthreads();
    for (int st = 512; st > 0; st >>= 1) {
        if (tid < st) { ss[tid] += ss[tid + st]; sq[tid] += sq[tid + st]; }
        __syncthreads();
    }
    if (tid == 0) {
        float N = (float)((size_t)NBATCH * GPTS);
        float m = ss[0] / N;
        float v = sq[0] / N - m * m;
        float inv = rsqrtf(v + EPSV);
        float a = gamma[o] * inv;
        float cc = beta[o] - a * m;
        aOut[o] = a;
        cOut[o] = cc;
        if (LAST) { sac[0] = a; sac[1] = cc; }
    }
    if (LAST) {
        __syncthreads();
        float a = sac[0], cc = sac[1];
        int b = tid >> 5, lane = tid & 31;
        const float* pm = d_Pmax + (size_t)o * NB + b * NTILE;
        const float* pn = d_Pmin + (size_t)o * NB + b * NTILE;
        float mx = fmaxf(pm[lane], pm[lane + 32]);
        float mn = fminf(pn[lane], pn[lane + 32]);
#pragma unroll
        for (int sh = 16; sh > 0; sh >>= 1) {
            mx = fmaxf(mx, __shfl_xor_sync(0xFFFFFFFFu, mx, sh));
            mn = fminf(mn, __shfl_xor_sync(0xFFFFFFFFu, mn, sh));
        }
        if (lane == 0) {
            float y = (a >= 0.f) ? mx : mn;
            out[b * OCH + o] = leaky(fmaf(a, y, cc));
        }
    }
}

// ---------------- launcher ----------------
extern "C" void kernel_launch(void* const* d_in, const int* in_sizes, int n_in,
                              void* d_out, int out_size)
{
    const float* feat = (const float*)d_in[0];
    const float* ev   = (const float*)d_in[1];
    const float* W[4] = {(const float*)d_in[2], (const float*)d_in[3],
                         (const float*)d_in[4], (const float*)d_in[5]};
    const float* gm[4] = {(const float*)d_in[6],  (const float*)d_in[8],
                          (const float*)d_in[10], (const float*)d_in[12]};
    const float* bt[4] = {(const float*)d_in[7],  (const float*)d_in[9],
                          (const float*)d_in[11], (const float*)d_in[13]};
    float* out = (float*)d_out;

    cudaFuncSetAttribute(gemm_mm<false>, cudaFuncAttributeMaxDynamicSharedMemorySize, SMB_DYN);
    cudaFuncSetAttribute(gemm_mm<true>,  cudaFuncAttributeMaxDynamicSharedMemorySize, SMB_DYN);

    float *y0, *y1, *aa, *cc, *w2t;
    uint32_t* wsw;
    cudaGetSymbolAddress((void**)&y0, d_Y0);
    cudaGetSymbolAddress((void**)&y1, d_Y1);
    cudaGetSymbolAddress((void**)&aa, d_Aa);
    cudaGetSymbolAddress((void**)&cc, d_Cc);
    cudaGetSymbolAddress((void**)&wsw, d_WhiSw);
    cudaGetSymbolAddress((void**)&w2t, d_W2T);

    int prepN = 4 * 6 * 2048 + 4 * OCH * OCH;
    prep_w_all<<<(prepN + 255) / 256, 256>>>(W[0], W[1], W[2], W[3]);

    float* ybuf[2] = {y0, y1};
    const float* cur = feat;
    int curC = 64;
    float* aPrev = nullptr;
    float* cPrev = nullptr;

    dim3 gg(NTILE, NBATCH);
    for (int L = 0; L < 4; L++) {
        int dst = L & 1;
        float* aCur = aa + dst * OCH;
        float* cCur = cc + dst * OCH;
        int nsec = (curC + 3 + KSEC - 1) / KSEC;      // 64->3, 128->5
        const uint32_t* Wsw = wsw + (size_t)L * 6 * 2048;
        const float* W2T = w2t + (size_t)L * OCH * OCH;
        prep_bias<<<NBATCH, 256>>>(W2T, curC, cur, aPrev, cPrev);
        if (L == 3) {
            gemm_mm<true><<<gg, 256, SMB_DYN>>>(cur, curC, nsec, Wsw, ev, aPrev, cPrev, ybuf[dst]);
            stats_kernel<true><<<OCH, 1024>>>(gm[L], bt[L], aCur, cCur, out);
        } else {
            gemm_mm<false><<<gg, 256, SMB_DYN>>>(cur, curC, nsec, Wsw, ev, aPrev, cPrev, ybuf[dst]);
            stats_kernel<false><<<OCH, 1024>>>(gm[L], bt[L], aCur, cCur, out);
        }
        cur = ybuf[dst];
        curC = OCH;
        aPrev = aCur;
        cPrev = cCur;
    }
}